// round 3
// baseline (speedup 1.0000x reference)
#include <cuda_runtime.h>
#include <math.h>

// Problem constants
#define NE  8
#define NH  1024
#define NI  2816
#define NTK 2
#define NT  2048
#define NA  (NT * NTK)   // 4096 routed assignments

// GEMM tiling
#define BM 64
#define BN 64
#define BK 16

// -------- scratch (static device globals; no runtime allocation) --------
__device__ int g_cnt[NE];
__device__ int g_off[NE];
__device__ int g_cur[NE];
__device__ int g_tok[NA];     // slot -> token id
__device__ int g_pos[NA];     // (t,k) -> slot
__device__ __align__(16) float g_act[(size_t)NA * NI];  // silu(g)*u, 46 MB
__device__ __align__(16) float g_y[(size_t)NA * NH];    // per-assignment down output, 17 MB

// ---------------- routing ----------------
__global__ void k_route_init() {
    int i = threadIdx.x;
    if (i < NE) g_cnt[i] = 0;
}

__global__ void k_route_count(const int* __restrict__ idx) {
    int i = blockIdx.x * blockDim.x + threadIdx.x;
    if (i < NA) atomicAdd(&g_cnt[idx[i]], 1);
}

__global__ void k_route_offsets() {
    int s = 0;
    for (int e = 0; e < NE; e++) {
        g_off[e] = s;
        g_cur[e] = s;
        s += g_cnt[e];
    }
}

__global__ void k_route_scatter(const int* __restrict__ idx) {
    int i = blockIdx.x * blockDim.x + threadIdx.x;
    if (i < NA) {
        int e = idx[i];
        int p = atomicAdd(&g_cur[e], 1);
        g_tok[p] = i / NTK;
        g_pos[i] = p;
    }
}

// ---------------- pass A: act = silu(X@Wg) * (X@Wu), grouped per expert ----------------
// grid: (m_tiles=NA/BM, c_tiles=NI/BN, NE) -- m fastest so concurrent blocks share
// the same weight columns (L2 reuse of Wg/Wu); X (8MB) is always L2-resident.
__global__ __launch_bounds__(256)
void k_gate_up(const float* __restrict__ hs,
               const float* __restrict__ wg,
               const float* __restrict__ wu) {
    const int e   = blockIdx.z;
    const int cnt = g_cnt[e];
    const int m0  = blockIdx.x * BM;
    if (m0 >= cnt) return;
    const int seg = g_off[e];
    const int c0  = blockIdx.y * BN;

    __shared__ float As[BK][BM];
    __shared__ float Bg[BK][BN];
    __shared__ float Bu[BK][BN];
    __shared__ int   rows[BM];

    const int tid = threadIdx.x;
    if (tid < BM) {
        int m = m0 + tid;
        rows[tid] = (m < cnt) ? g_tok[seg + m] : -1;
    }
    __syncthreads();

    const int tx = tid & 15;   // output col quad
    const int ty = tid >> 4;   // output row quad

    // A-tile load mapping: each thread loads 4 consecutive k for one gathered row
    const int am   = tid & 63;
    const int ak4  = tid >> 6;      // 0..3
    const int arow = rows[am];
    const float* ap = (arow >= 0) ? (hs + (size_t)arow * NH + ak4 * 4) : hs;

    // B-tile load mapping: float4 along n
    const int bn4 = tid & 15;
    const int bk  = tid >> 4;
    const float* wgp = wg + (size_t)e * NH * NI + (size_t)bk * NI + c0 + bn4 * 4;
    const float* wup = wu + (size_t)e * NH * NI + (size_t)bk * NI + c0 + bn4 * 4;

    float ag[4][4], au[4][4];
#pragma unroll
    for (int i = 0; i < 4; i++)
#pragma unroll
        for (int j = 0; j < 4; j++) { ag[i][j] = 0.f; au[i][j] = 0.f; }

    for (int k0 = 0; k0 < NH; k0 += BK) {
        float4 av = make_float4(0.f, 0.f, 0.f, 0.f);
        if (arow >= 0) av = *(const float4*)(ap + k0);
        float4 bgv = *(const float4*)(wgp + (size_t)k0 * NI);
        float4 buv = *(const float4*)(wup + (size_t)k0 * NI);

        As[ak4 * 4 + 0][am] = av.x;
        As[ak4 * 4 + 1][am] = av.y;
        As[ak4 * 4 + 2][am] = av.z;
        As[ak4 * 4 + 3][am] = av.w;
        *(float4*)&Bg[bk][bn4 * 4] = bgv;
        *(float4*)&Bu[bk][bn4 * 4] = buv;
        __syncthreads();

#pragma unroll
        for (int kk = 0; kk < BK; kk++) {
            float4 a4 = *(const float4*)&As[kk][ty * 4];
            float4 g4 = *(const float4*)&Bg[kk][tx * 4];
            float4 u4 = *(const float4*)&Bu[kk][tx * 4];
            float aa[4] = {a4.x, a4.y, a4.z, a4.w};
            float gg[4] = {g4.x, g4.y, g4.z, g4.w};
            float uu[4] = {u4.x, u4.y, u4.z, u4.w};
#pragma unroll
            for (int i = 0; i < 4; i++)
#pragma unroll
                for (int j = 0; j < 4; j++) {
                    ag[i][j] += aa[i] * gg[j];
                    au[i][j] += aa[i] * uu[j];
                }
        }
        __syncthreads();
    }

#pragma unroll
    for (int i = 0; i < 4; i++) {
        int m = m0 + ty * 4 + i;
        if (m < cnt) {
            float r[4];
#pragma unroll
            for (int j = 0; j < 4; j++) {
                float g = ag[i][j];
                float s = g / (1.f + expf(-g));   // silu
                r[j] = s * au[i][j];
            }
            float4 o = make_float4(r[0], r[1], r[2], r[3]);
            *(float4*)&g_act[(size_t)(seg + m) * NI + c0 + tx * 4] = o;
        }
    }
}

// ---------------- pass B: y = act @ Wd, grouped per expert ----------------
__global__ __launch_bounds__(256)
void k_down(const float* __restrict__ wd) {
    const int e   = blockIdx.z;
    const int cnt = g_cnt[e];
    const int m0  = blockIdx.x * BM;
    if (m0 >= cnt) return;
    const int seg = g_off[e];
    const int h0  = blockIdx.y * BN;

    __shared__ float As[BK][BM];
    __shared__ float Bs[BK][BN];

    const int tid = threadIdx.x;
    const int tx = tid & 15;
    const int ty = tid >> 4;

    const int am  = tid & 63;
    const int ak4 = tid >> 6;
    const bool avalid = (m0 + am) < cnt;
    const float* ap = g_act + (size_t)(seg + (avalid ? (m0 + am) : 0)) * NI + ak4 * 4;

    const int bn4 = tid & 15;
    const int bk  = tid >> 4;
    const float* bp = wd + (size_t)e * NI * NH + (size_t)bk * NH + h0 + bn4 * 4;

    float acc[4][4];
#pragma unroll
    for (int i = 0; i < 4; i++)
#pragma unroll
        for (int j = 0; j < 4; j++) acc[i][j] = 0.f;

    for (int k0 = 0; k0 < NI; k0 += BK) {
        float4 av = avalid ? *(const float4*)(ap + k0) : make_float4(0.f, 0.f, 0.f, 0.f);
        float4 bv = *(const float4*)(bp + (size_t)k0 * NH);

        As[ak4 * 4 + 0][am] = av.x;
        As[ak4 * 4 + 1][am] = av.y;
        As[ak4 * 4 + 2][am] = av.z;
        As[ak4 * 4 + 3][am] = av.w;
        *(float4*)&Bs[bk][bn4 * 4] = bv;
        __syncthreads();

#pragma unroll
        for (int kk = 0; kk < BK; kk++) {
            float4 a4 = *(const float4*)&As[kk][ty * 4];
            float4 b4 = *(const float4*)&Bs[kk][tx * 4];
            float aa[4] = {a4.x, a4.y, a4.z, a4.w};
            float bb[4] = {b4.x, b4.y, b4.z, b4.w};
#pragma unroll
            for (int i = 0; i < 4; i++)
#pragma unroll
                for (int j = 0; j < 4; j++)
                    acc[i][j] += aa[i] * bb[j];
        }
        __syncthreads();
    }

#pragma unroll
    for (int i = 0; i < 4; i++) {
        int m = m0 + ty * 4 + i;
        if (m < cnt) {
            float4 o = make_float4(acc[i][0], acc[i][1], acc[i][2], acc[i][3]);
            *(float4*)&g_y[(size_t)(seg + m) * NH + h0 + tx * 4] = o;
        }
    }
}

// ---------------- combine: out[t] = sum_k w[t,k] * y[slot(t,k)] ----------------
// Deterministic (fixed k order), no atomics into out.
__global__ void k_combine(const float* __restrict__ val, float* __restrict__ out) {
    int i = blockIdx.x * blockDim.x + threadIdx.x;
    if (i >= NT * (NH / 4)) return;
    int t  = i / (NH / 4);
    int h4 = i - t * (NH / 4);
    float4 r = make_float4(0.f, 0.f, 0.f, 0.f);
#pragma unroll
    for (int k = 0; k < NTK; k++) {
        int   p = g_pos[t * NTK + k];
        float w = val[t * NTK + k];
        float4 y = *(const float4*)&g_y[(size_t)p * NH + h4 * 4];
        r.x += w * y.x;
        r.y += w * y.y;
        r.z += w * y.z;
        r.w += w * y.w;
    }
    *(float4*)&out[(size_t)t * NH + h4 * 4] = r;
}

// ---------------- launch ----------------
extern "C" void kernel_launch(void* const* d_in, const int* in_sizes, int n_in,
                              void* d_out, int out_size) {
    const float* hs  = (const float*)d_in[0];   // hidden_states [T,H]
    const int*   idx = (const int*)d_in[1];     // top_k_indices [T,K]
    const float* val = (const float*)d_in[2];   // top_k_values  [T,K]
    const float* wg  = (const float*)d_in[3];   // w_gate [E,H,I]
    const float* wu  = (const float*)d_in[4];   // w_up   [E,H,I]
    const float* wd  = (const float*)d_in[5];   // w_down [E,I,H]
    float*       out = (float*)d_out;           // [T,H]

    (void)in_sizes; (void)n_in; (void)out_size;

    k_route_init<<<1, 32>>>();
    k_route_count<<<(NA + 255) / 256, 256>>>(idx);
    k_route_offsets<<<1, 1>>>();
    k_route_scatter<<<(NA + 255) / 256, 256>>>(idx);

    dim3 gA(NA / BM, NI / BN, NE);   // (64, 44, 8); inactive m-tiles early-exit
    k_gate_up<<<gA, 256>>>(hs, wg, wu);

    dim3 gB(NA / BM, NH / BN, NE);   // (64, 16, 8)
    k_down<<<gB, 256>>>(wd);

    k_combine<<<(NT * (NH / 4) + 255) / 256, 256>>>(val, out);
}

// round 5
// speedup vs baseline: 2.0713x; 2.0713x over previous
#include <cuda_runtime.h>
#include <cuda_bf16.h>
#include <cstdint>
#include <math.h>

// Problem constants
#define NE  8
#define NH  1024
#define NI  2816
#define NTK 2
#define NT  2048
#define NA  (NT * NTK)

// strides (bf16 elements) with padding for conflict-free ldmatrix
#define A_STR  40    // BK=32 + 8
#define B1_STR 72    // 64 + 8
#define B2_STR 136   // 128 + 8

// -------- scratch --------
__device__ int g_cnt[NE];
__device__ int g_off[NE];
__device__ int g_cur[NE];
__device__ int g_tok[NA];
__device__ int g_pos[NA];
__device__ __align__(16) float g_act[(size_t)NA * NI];
__device__ __align__(16) float g_y[(size_t)NA * NH];

// ---------------- helpers ----------------
__device__ __forceinline__ uint32_t smem_u32(const void* p) {
    uint32_t a;
    asm("{ .reg .u64 t; cvta.to.shared.u64 t, %1; cvt.u32.u64 %0, t; }" : "=r"(a) : "l"(p));
    return a;
}
__device__ __forceinline__ void ldsm_x4(uint32_t* r, uint32_t a) {
    asm volatile("ldmatrix.sync.aligned.m8n8.x4.shared.b16 {%0,%1,%2,%3}, [%4];"
                 : "=r"(r[0]), "=r"(r[1]), "=r"(r[2]), "=r"(r[3]) : "r"(a));
}
__device__ __forceinline__ void ldsm_x2t(uint32_t* r, uint32_t a) {
    asm volatile("ldmatrix.sync.aligned.m8n8.x2.trans.shared.b16 {%0,%1}, [%2];"
                 : "=r"(r[0]), "=r"(r[1]) : "r"(a));
}
__device__ __forceinline__ void mma16816(float* d, const uint32_t* a, const uint32_t* b) {
    asm volatile("mma.sync.aligned.m16n8k16.row.col.f32.bf16.bf16.f32 "
                 "{%0,%1,%2,%3}, {%4,%5,%6,%7}, {%8,%9}, {%0,%1,%2,%3};"
                 : "+f"(d[0]), "+f"(d[1]), "+f"(d[2]), "+f"(d[3])
                 : "r"(a[0]), "r"(a[1]), "r"(a[2]), "r"(a[3]), "r"(b[0]), "r"(b[1]));
}
__device__ __forceinline__ void split2(float x0, float x1, uint32_t& hi, uint32_t& lo) {
    __nv_bfloat16 h0 = __float2bfloat16(x0);
    __nv_bfloat16 h1 = __float2bfloat16(x1);
    __nv_bfloat16 l0 = __float2bfloat16(x0 - __bfloat162float(h0));
    __nv_bfloat16 l1 = __float2bfloat16(x1 - __bfloat162float(h1));
    union { __nv_bfloat162 b; uint32_t u; } ch, cl;
    ch.b = __halves2bfloat162(h0, h1);
    cl.b = __halves2bfloat162(l0, l1);
    hi = ch.u; lo = cl.u;
}
// split 16 fp32 -> two uint4 hi + two uint4 lo, store to smem
__device__ __forceinline__ void split_store16(const float* v, uint16_t* dhi, uint16_t* dlo) {
    uint32_t h[8], l[8];
#pragma unroll
    for (int p = 0; p < 8; p++) split2(v[2 * p], v[2 * p + 1], h[p], l[p]);
    ((uint4*)dhi)[0] = make_uint4(h[0], h[1], h[2], h[3]);
    ((uint4*)dhi)[1] = make_uint4(h[4], h[5], h[6], h[7]);
    ((uint4*)dlo)[0] = make_uint4(l[0], l[1], l[2], l[3]);
    ((uint4*)dlo)[1] = make_uint4(l[4], l[5], l[6], l[7]);
}

// ---------------- routing ----------------
__global__ void k_route_init() { if (threadIdx.x < NE) g_cnt[threadIdx.x] = 0; }
__global__ void k_route_count(const int* __restrict__ idx) {
    int i = blockIdx.x * blockDim.x + threadIdx.x;
    if (i < NA) atomicAdd(&g_cnt[idx[i]], 1);
}
__global__ void k_route_offsets() {
    int s = 0;
    for (int e = 0; e < NE; e++) { g_off[e] = s; g_cur[e] = s; s += g_cnt[e]; }
}
__global__ void k_route_scatter(const int* __restrict__ idx) {
    int i = blockIdx.x * blockDim.x + threadIdx.x;
    if (i < NA) {
        int e = idx[i];
        int p = atomicAdd(&g_cur[e], 1);
        g_tok[p] = i / NTK;
        g_pos[i] = p;
    }
}

// ---------------- GEMM1: act = silu(X@Wg) * (X@Wu) ----------------
// CTA tile 128m x 64n, BK=32, 8 warps (4m x 2n), warp tile 32x32 per matrix.
__global__ __launch_bounds__(256)
void k_gate_up_mma(const float* __restrict__ hs,
                   const float* __restrict__ wg,
                   const float* __restrict__ wu) {
    const int e   = blockIdx.z;
    const int cnt = g_cnt[e];
    const int m0  = blockIdx.x * 128;
    if (m0 >= cnt) return;
    const int seg = g_off[e];
    const int c0  = blockIdx.y * 64;

    __shared__ uint16_t As_hi[128 * A_STR], As_lo[128 * A_STR];
    __shared__ uint16_t Bg_hi[32 * B1_STR], Bg_lo[32 * B1_STR];
    __shared__ uint16_t Bu_hi[32 * B1_STR], Bu_lo[32 * B1_STR];
    __shared__ int rows[128];

    const int tid = threadIdx.x;
    const int lane = tid & 31, wid = tid >> 5;
    const int wm = wid & 3, wn = wid >> 2;

    if (tid < 128) rows[tid] = (m0 + tid < cnt) ? g_tok[seg + m0 + tid] : -1;
    __syncthreads();

    // load mappings
    const int am = tid >> 1, ak = (tid & 1) * 16;
    const int arow = rows[am];
    const float* apA = (arow >= 0) ? (hs + (size_t)arow * NH + ak) : nullptr;

    const int half = tid >> 7;                 // 0: gate, 1: up
    const int bt = tid & 127;
    const int bk = bt >> 2, bn = (bt & 3) * 16;
    const float* apB = (half ? wu : wg) + (size_t)e * NH * NI + (size_t)bk * NI + c0 + bn;
    uint16_t* Bhi = half ? Bu_hi : Bg_hi;
    uint16_t* Blo = half ? Bu_lo : Bg_lo;

    const uint32_t sAh = smem_u32(As_hi), sAl = smem_u32(As_lo);
    const uint32_t sGh = smem_u32(Bg_hi), sGl = smem_u32(Bg_lo);
    const uint32_t sUh = smem_u32(Bu_hi), sUl = smem_u32(Bu_lo);

    float dg[2][4][4], du[2][4][4];
#pragma unroll
    for (int i = 0; i < 2; i++)
#pragma unroll
        for (int j = 0; j < 4; j++)
#pragma unroll
            for (int q = 0; q < 4; q++) { dg[i][j][q] = 0.f; du[i][j][q] = 0.f; }

    float va[16], vb[16];
    // prefetch chunk 0
#pragma unroll
    for (int q = 0; q < 4; q++) {
        float4 t = apA ? ((const float4*)apA)[q] : make_float4(0.f, 0.f, 0.f, 0.f);
        va[4 * q] = t.x; va[4 * q + 1] = t.y; va[4 * q + 2] = t.z; va[4 * q + 3] = t.w;
        float4 s = ((const float4*)apB)[q];
        vb[4 * q] = s.x; vb[4 * q + 1] = s.y; vb[4 * q + 2] = s.z; vb[4 * q + 3] = s.w;
    }

    const int NC = NH / 32;
    for (int c = 0; c < NC; c++) {
        split_store16(va, &As_hi[am * A_STR + ak], &As_lo[am * A_STR + ak]);
        split_store16(vb, &Bhi[bk * B1_STR + bn], &Blo[bk * B1_STR + bn]);
        __syncthreads();

        if (c + 1 < NC) {
            const float*  pa = apA ? (apA + (size_t)(c + 1) * 32) : nullptr;
            const float*  pb = apB + (size_t)(c + 1) * 32 * NI;
#pragma unroll
            for (int q = 0; q < 4; q++) {
                float4 t = pa ? ((const float4*)pa)[q] : make_float4(0.f, 0.f, 0.f, 0.f);
                va[4 * q] = t.x; va[4 * q + 1] = t.y; va[4 * q + 2] = t.z; va[4 * q + 3] = t.w;
                float4 s = ((const float4*)pb)[q];
                vb[4 * q] = s.x; vb[4 * q + 1] = s.y; vb[4 * q + 2] = s.z; vb[4 * q + 3] = s.w;
            }
        }

#pragma unroll
        for (int ks = 0; ks < 2; ks++) {
            const int k16 = ks * 16;
            uint32_t ah[2][4], al[2][4];
#pragma unroll
            for (int i = 0; i < 2; i++) {
                int row = wm * 32 + i * 16 + (lane & 15);
                int col = k16 + (lane >> 4) * 8;
                uint32_t off = (uint32_t)(row * A_STR + col) * 2;
                ldsm_x4(ah[i], sAh + off);
                ldsm_x4(al[i], sAl + off);
            }
#pragma unroll
            for (int j = 0; j < 4; j++) {
                int n = wn * 32 + j * 8;
                uint32_t off = (uint32_t)((k16 + (lane & 15)) * B1_STR + n) * 2;
                uint32_t bh[2], bl[2];
                ldsm_x2t(bh, sGh + off);
                ldsm_x2t(bl, sGl + off);
#pragma unroll
                for (int i = 0; i < 2; i++) {
                    mma16816(dg[i][j], ah[i], bh);
                    mma16816(dg[i][j], ah[i], bl);
                    mma16816(dg[i][j], al[i], bh);
                }
                ldsm_x2t(bh, sUh + off);
                ldsm_x2t(bl, sUl + off);
#pragma unroll
                for (int i = 0; i < 2; i++) {
                    mma16816(du[i][j], ah[i], bh);
                    mma16816(du[i][j], ah[i], bl);
                    mma16816(du[i][j], al[i], bh);
                }
            }
        }
        __syncthreads();
    }

    // epilogue: silu(g) * u
#pragma unroll
    for (int i = 0; i < 2; i++)
#pragma unroll
        for (int h = 0; h < 2; h++) {
            int m = m0 + wm * 32 + i * 16 + h * 8 + (lane >> 2);
            if (m < cnt) {
                float* op = g_act + (size_t)(seg + m) * NI + c0 + wn * 32 + (lane & 3) * 2;
#pragma unroll
                for (int j = 0; j < 4; j++) {
                    float g0 = dg[i][j][h * 2], g1 = dg[i][j][h * 2 + 1];
                    float u0 = du[i][j][h * 2], u1 = du[i][j][h * 2 + 1];
                    float r0 = g0 / (1.f + __expf(-g0)) * u0;
                    float r1 = g1 / (1.f + __expf(-g1)) * u1;
                    *(float2*)(op + j * 8) = make_float2(r0, r1);
                }
            }
        }
}

// ---------------- GEMM2: y = act @ Wd ----------------
// CTA tile 128m x 128n, BK=32, 8 warps (4m x 2n), warp tile 32x64.
__global__ __launch_bounds__(256)
void k_down_mma(const float* __restrict__ wd) {
    const int e   = blockIdx.z;
    const int cnt = g_cnt[e];
    const int m0  = blockIdx.x * 128;
    if (m0 >= cnt) return;
    const int seg = g_off[e];
    const int h0  = blockIdx.y * 128;

    __shared__ uint16_t As_hi[128 * A_STR], As_lo[128 * A_STR];
    __shared__ uint16_t Bs_hi[32 * B2_STR], Bs_lo[32 * B2_STR];

    const int tid = threadIdx.x;
    const int lane = tid & 31, wid = tid >> 5;
    const int wm = wid & 3, wn = wid >> 2;

    const int am = tid >> 1, ak = (tid & 1) * 16;
    const bool avalid = (m0 + am) < cnt;
    const float* apA = avalid ? (g_act + (size_t)(seg + m0 + am) * NI + ak) : nullptr;

    const int bk = tid >> 3, bn = (tid & 7) * 16;
    const float* apB = wd + (size_t)e * NI * NH + (size_t)bk * NH + h0 + bn;

    const uint32_t sAh = smem_u32(As_hi), sAl = smem_u32(As_lo);
    const uint32_t sBh = smem_u32(Bs_hi), sBl = smem_u32(Bs_lo);

    float acc[2][8][4];
#pragma unroll
    for (int i = 0; i < 2; i++)
#pragma unroll
        for (int j = 0; j < 8; j++)
#pragma unroll
            for (int q = 0; q < 4; q++) acc[i][j][q] = 0.f;

    float va[16], vb[16];
#pragma unroll
    for (int q = 0; q < 4; q++) {
        float4 t = apA ? ((const float4*)apA)[q] : make_float4(0.f, 0.f, 0.f, 0.f);
        va[4 * q] = t.x; va[4 * q + 1] = t.y; va[4 * q + 2] = t.z; va[4 * q + 3] = t.w;
        float4 s = ((const float4*)apB)[q];
        vb[4 * q] = s.x; vb[4 * q + 1] = s.y; vb[4 * q + 2] = s.z; vb[4 * q + 3] = s.w;
    }

    const int NC = NI / 32;
    for (int c = 0; c < NC; c++) {
        split_store16(va, &As_hi[am * A_STR + ak], &As_lo[am * A_STR + ak]);
        split_store16(vb, &Bs_hi[bk * B2_STR + bn], &Bs_lo[bk * B2_STR + bn]);
        __syncthreads();

        if (c + 1 < NC) {
            const float* pa = apA ? (apA + (size_t)(c + 1) * 32) : nullptr;
            const float* pb = apB + (size_t)(c + 1) * 32 * NH;
#pragma unroll
            for (int q = 0; q < 4; q++) {
                float4 t = pa ? ((const float4*)pa)[q] : make_float4(0.f, 0.f, 0.f, 0.f);
                va[4 * q] = t.x; va[4 * q + 1] = t.y; va[4 * q + 2] = t.z; va[4 * q + 3] = t.w;
                float4 s = ((const float4*)pb)[q];
                vb[4 * q] = s.x; vb[4 * q + 1] = s.y; vb[4 * q + 2] = s.z; vb[4 * q + 3] = s.w;
            }
        }

#pragma unroll
        for (int ks = 0; ks < 2; ks++) {
            const int k16 = ks * 16;
            uint32_t ah[2][4], al[2][4];
#pragma unroll
            for (int i = 0; i < 2; i++) {
                int row = wm * 32 + i * 16 + (lane & 15);
                int col = k16 + (lane >> 4) * 8;
                uint32_t off = (uint32_t)(row * A_STR + col) * 2;
                ldsm_x4(ah[i], sAh + off);
                ldsm_x4(al[i], sAl + off);
            }
#pragma unroll
            for (int j = 0; j < 8; j++) {
                int n = wn * 64 + j * 8;
                uint32_t off = (uint32_t)((k16 + (lane & 15)) * B2_STR + n) * 2;
                uint32_t bh[2], bl[2];
                ldsm_x2t(bh, sBh + off);
                ldsm_x2t(bl, sBl + off);
#pragma unroll
                for (int i = 0; i < 2; i++) {
                    mma16816(acc[i][j], ah[i], bh);
                    mma16816(acc[i][j], ah[i], bl);
                    mma16816(acc[i][j], al[i], bh);
                }
            }
        }
        __syncthreads();
    }

#pragma unroll
    for (int i = 0; i < 2; i++)
#pragma unroll
        for (int h = 0; h < 2; h++) {
            int m = m0 + wm * 32 + i * 16 + h * 8 + (lane >> 2);
            if (m < cnt) {
                float* op = g_y + (size_t)(seg + m) * NH + h0 + wn * 64 + (lane & 3) * 2;
#pragma unroll
                for (int j = 0; j < 8; j++)
                    *(float2*)(op + j * 8) = make_float2(acc[i][j][h * 2], acc[i][j][h * 2 + 1]);
            }
        }
}

// ---------------- combine ----------------
__global__ void k_combine(const float* __restrict__ val, float* __restrict__ out) {
    int i = blockIdx.x * blockDim.x + threadIdx.x;
    if (i >= NT * (NH / 4)) return;
    int t  = i / (NH / 4);
    int h4 = i - t * (NH / 4);
    float4 r = make_float4(0.f, 0.f, 0.f, 0.f);
#pragma unroll
    for (int k = 0; k < NTK; k++) {
        int   p = g_pos[t * NTK + k];
        float w = val[t * NTK + k];
        float4 y = *(const float4*)&g_y[(size_t)p * NH + h4 * 4];
        r.x += w * y.x; r.y += w * y.y; r.z += w * y.z; r.w += w * y.w;
    }
    *(float4*)&out[(size_t)t * NH + h4 * 4] = r;
}

// ---------------- launch ----------------
extern "C" void kernel_launch(void* const* d_in, const int* in_sizes, int n_in,
                              void* d_out, int out_size) {
    const float* hs  = (const float*)d_in[0];
    const int*   idx = (const int*)d_in[1];
    const float* val = (const float*)d_in[2];
    const float* wg  = (const float*)d_in[3];
    const float* wu  = (const float*)d_in[4];
    const float* wd  = (const float*)d_in[5];
    float*       out = (float*)d_out;
    (void)in_sizes; (void)n_in; (void)out_size;

    k_route_init<<<1, 32>>>();
    k_route_count<<<(NA + 255) / 256, 256>>>(idx);
    k_route_offsets<<<1, 1>>>();
    k_route_scatter<<<(NA + 255) / 256, 256>>>(idx);

    dim3 g1(NA / 128, NI / 64, NE);    // (32, 44, 8), m fastest for L2 weight sharing
    k_gate_up_mma<<<g1, 256>>>(hs, wg, wu);

    dim3 g2(NA / 128, NH / 128, NE);   // (32, 8, 8)
    k_down_mma<<<g2, 256>>>(wd);

    k_combine<<<(NT * (NH / 4) + 255) / 256, 256>>>(val, out);
}

// round 9
// speedup vs baseline: 2.3959x; 1.1567x over previous
#include <cuda_runtime.h>
#include <cuda_bf16.h>
#include <cstdint>

// Problem constants
#define NE  8
#define NH  1024
#define NI  2816
#define NTK 2
#define NT  2048
#define NA  (NT * NTK)

// smem strides (bf16 elements), padded for conflict-free ldmatrix
#define A_STR  40    // 32 + 8
#define B1_STR 72    // 64 + 8
#define B2_STR 136   // 128 + 8

// -------- scratch (static device globals) --------
__device__ int g_cnt[NE];
__device__ int g_off[NE];
__device__ int g_tok[NA];
__device__ int g_pos[NA];
__device__ __align__(16) uint16_t g_xhi[NT * NH];                 // 4MB
__device__ __align__(16) uint16_t g_xlo[NT * NH];                 // 4MB
__device__ __align__(16) uint16_t g_act_hi[(size_t)NA * NI];      // 23MB
__device__ __align__(16) uint16_t g_act_lo[(size_t)NA * NI];      // 23MB
__device__ __align__(16) float    g_y[(size_t)NA * NH];           // 17MB

// ---------------- helpers ----------------
__device__ __forceinline__ uint32_t smem_u32(const void* p) {
    uint32_t a;
    asm("{ .reg .u64 t; cvta.to.shared.u64 t, %1; cvt.u32.u64 %0, t; }" : "=r"(a) : "l"(p));
    return a;
}
__device__ __forceinline__ void ldsm_x4(uint32_t* r, uint32_t a) {
    asm volatile("ldmatrix.sync.aligned.m8n8.x4.shared.b16 {%0,%1,%2,%3}, [%4];"
                 : "=r"(r[0]), "=r"(r[1]), "=r"(r[2]), "=r"(r[3]) : "r"(a));
}
__device__ __forceinline__ void ldsm_x2t(uint32_t* r, uint32_t a) {
    asm volatile("ldmatrix.sync.aligned.m8n8.x2.trans.shared.b16 {%0,%1}, [%2];"
                 : "=r"(r[0]), "=r"(r[1]) : "r"(a));
}
__device__ __forceinline__ void mma16816(float* d, const uint32_t* a, const uint32_t* b) {
    asm volatile("mma.sync.aligned.m16n8k16.row.col.f32.bf16.bf16.f32 "
                 "{%0,%1,%2,%3}, {%4,%5,%6,%7}, {%8,%9}, {%0,%1,%2,%3};"
                 : "+f"(d[0]), "+f"(d[1]), "+f"(d[2]), "+f"(d[3])
                 : "r"(a[0]), "r"(a[1]), "r"(a[2]), "r"(a[3]), "r"(b[0]), "r"(b[1]));
}
// fast split: hi = truncated-bf16 (exact top-16-bits), lo = rn-bf16 of residual
__device__ __forceinline__ void fsplit2(float x0, float x1, uint32_t& hi, uint32_t& lo) {
    uint32_t u0 = __float_as_uint(x0), u1 = __float_as_uint(x1);
    hi = __byte_perm(u0, u1, 0x7632);
    float r0 = x0 - __uint_as_float(u0 & 0xFFFF0000u);
    float r1 = x1 - __uint_as_float(u1 & 0xFFFF0000u);
    __nv_bfloat162 p = __floats2bfloat162_rn(r0, r1);
    lo = *(uint32_t*)&p;
}
// 16 fp32 -> 8x u32 hi + 8x u32 lo
__device__ __forceinline__ void split16(const float* v, uint32_t* h, uint32_t* l) {
#pragma unroll
    for (int p = 0; p < 8; p++) fsplit2(v[2 * p], v[2 * p + 1], h[p], l[p]);
}

// ---------------- launch 0: routing (single block) ----------------
__global__ void k_route(const int* __restrict__ idx) {
    __shared__ int sc[NE], scur[NE];
    int tid = threadIdx.x;
    if (tid < NE) sc[tid] = 0;
    __syncthreads();
    for (int i = tid; i < NA; i += 1024) atomicAdd(&sc[idx[i]], 1);
    __syncthreads();
    if (tid == 0) {
        int s = 0;
        for (int e = 0; e < NE; e++) { g_cnt[e] = sc[e]; g_off[e] = s; scur[e] = s; s += sc[e]; }
    }
    __syncthreads();
    for (int i = tid; i < NA; i += 1024) {
        int e = idx[i];
        int p = atomicAdd(&scur[e], 1);
        g_tok[p] = i / NTK;
        g_pos[i] = p;
    }
}

// ---------------- launches 1,2: pre-split X into bf16 hi/lo ----------------
__global__ void k_split_x(const float* __restrict__ hs, int rowbase) {
    int i = blockIdx.x * blockDim.x + threadIdx.x;     // one thread per 8 elems
    size_t base = (size_t)rowbase * NH + (size_t)i * 8;
    float4 v0 = ((const float4*)(hs + base))[0];
    float4 v1 = ((const float4*)(hs + base))[1];
    float v[8] = {v0.x, v0.y, v0.z, v0.w, v1.x, v1.y, v1.z, v1.w};
    uint32_t h[4], l[4];
#pragma unroll
    for (int p = 0; p < 4; p++) fsplit2(v[2 * p], v[2 * p + 1], h[p], l[p]);
    *(uint4*)&g_xhi[base] = make_uint4(h[0], h[1], h[2], h[3]);
    *(uint4*)&g_xlo[base] = make_uint4(l[0], l[1], l[2], l[3]);
}

// ---------------- launch 3: GEMM1 act = silu(X@Wg)*(X@Wu) ----------------
// CTA 128m x 64n, BK=32, double-buffered smem, 8 warps (4m x 2n), warp tile 32x32.
#define STG1 38912
__global__ __launch_bounds__(256)
void k_gate_up(const float* __restrict__ wg, const float* __restrict__ wu) {
    const int e   = blockIdx.z;
    const int cnt = g_cnt[e];
    const int m0  = blockIdx.x * 128;
    if (m0 >= cnt) return;
    const int seg = g_off[e];
    const int c0  = blockIdx.y * 64;

    extern __shared__ char smem[];
    __shared__ int rows[128];

    const int tid = threadIdx.x;
    const int lane = tid & 31, wid = tid >> 5;
    const int wm = wid & 3, wn = wid >> 2;

    if (tid < 128) rows[tid] = (m0 + tid < cnt) ? g_tok[seg + m0 + tid] : g_tok[seg];
    __syncthreads();

    // A load mapping (bf16 direct copy): row am, cols ak..ak+15
    const int am = tid >> 1, ak = (tid & 1) * 16;
    const int arow = rows[am];
    const uint16_t* pxh = g_xhi + (size_t)arow * NH + ak;
    const uint16_t* pxl = g_xlo + (size_t)arow * NH + ak;

    // B load mapping: half 0 = gate, 1 = up
    const int half = tid >> 7;
    const int bt = tid & 127;
    const int bk = bt >> 2, bn = (bt & 3) * 16;
    const float* apB = (half ? wu : wg) + (size_t)e * NH * NI + (size_t)bk * NI + c0 + bn;

    const uint32_t sb = smem_u32(smem);
    // stage offsets (bytes)
    const uint32_t OAH = 0, OAL = 10240, OGH = 20480, OGL = 25088, OUH = 29696, OUL = 34304;
    const uint32_t obh = half ? OUH : OGH;
    const uint32_t obl = half ? OUL : OGL;

    float dg[2][4][4], du[2][4][4];
#pragma unroll
    for (int i = 0; i < 2; i++)
#pragma unroll
        for (int j = 0; j < 4; j++)
#pragma unroll
            for (int q = 0; q < 4; q++) { dg[i][j][q] = 0.f; du[i][j][q] = 0.f; }

    uint4 ahv[2], alv[2];
    float vb[16];

    // preload chunk 0
    ahv[0] = ((const uint4*)pxh)[0]; ahv[1] = ((const uint4*)pxh)[1];
    alv[0] = ((const uint4*)pxl)[0]; alv[1] = ((const uint4*)pxl)[1];
#pragma unroll
    for (int q = 0; q < 4; q++) {
        float4 s = ((const float4*)apB)[q];
        vb[4 * q] = s.x; vb[4 * q + 1] = s.y; vb[4 * q + 2] = s.z; vb[4 * q + 3] = s.w;
    }
    // store stage 0
    {
        char* st = smem;
        *(uint4*)(st + OAH + (am * A_STR + ak) * 2) = ahv[0];
        *(uint4*)(st + OAH + (am * A_STR + ak + 8) * 2) = ahv[1];
        *(uint4*)(st + OAL + (am * A_STR + ak) * 2) = alv[0];
        *(uint4*)(st + OAL + (am * A_STR + ak + 8) * 2) = alv[1];
        uint32_t h[8], l[8];
        split16(vb, h, l);
        *(uint4*)(st + obh + (bk * B1_STR + bn) * 2) = make_uint4(h[0], h[1], h[2], h[3]);
        *(uint4*)(st + obh + (bk * B1_STR + bn + 8) * 2) = make_uint4(h[4], h[5], h[6], h[7]);
        *(uint4*)(st + obl + (bk * B1_STR + bn) * 2) = make_uint4(l[0], l[1], l[2], l[3]);
        *(uint4*)(st + obl + (bk * B1_STR + bn + 8) * 2) = make_uint4(l[4], l[5], l[6], l[7]);
    }
    __syncthreads();

    const int NC = NH / 32;
    for (int c = 0; c < NC; c++) {
        const uint32_t cur = (uint32_t)(c & 1) * STG1;
        const uint32_t nxt = cur ^ STG1;
        // prefetch chunk c+1
        if (c + 1 < NC) {
            const uint16_t* ph = pxh + (c + 1) * 32;
            const uint16_t* pl = pxl + (c + 1) * 32;
            ahv[0] = ((const uint4*)ph)[0]; ahv[1] = ((const uint4*)ph)[1];
            alv[0] = ((const uint4*)pl)[0]; alv[1] = ((const uint4*)pl)[1];
            const float* pb = apB + (size_t)(c + 1) * 32 * NI;
#pragma unroll
            for (int q = 0; q < 4; q++) {
                float4 s = ((const float4*)pb)[q];
                vb[4 * q] = s.x; vb[4 * q + 1] = s.y; vb[4 * q + 2] = s.z; vb[4 * q + 3] = s.w;
            }
        }
        // MMA on stage cur
#pragma unroll
        for (int ks = 0; ks < 2; ks++) {
            const int k16 = ks * 16;
            uint32_t ah[2][4], al[2][4];
#pragma unroll
            for (int i = 0; i < 2; i++) {
                int row = wm * 32 + i * 16 + (lane & 15);
                int col = k16 + (lane >> 4) * 8;
                uint32_t off = (uint32_t)(row * A_STR + col) * 2;
                ldsm_x4(ah[i], sb + cur + OAH + off);
                ldsm_x4(al[i], sb + cur + OAL + off);
            }
#pragma unroll
            for (int j = 0; j < 4; j++) {
                int n = wn * 32 + j * 8;
                uint32_t off = (uint32_t)((k16 + (lane & 15)) * B1_STR + n) * 2;
                uint32_t bh[2], bl[2];
                ldsm_x2t(bh, sb + cur + OGH + off);
                ldsm_x2t(bl, sb + cur + OGL + off);
#pragma unroll
                for (int i = 0; i < 2; i++) {
                    mma16816(dg[i][j], ah[i], bh);
                    mma16816(dg[i][j], ah[i], bl);
                    mma16816(dg[i][j], al[i], bh);
                }
                ldsm_x2t(bh, sb + cur + OUH + off);
                ldsm_x2t(bl, sb + cur + OUL + off);
#pragma unroll
                for (int i = 0; i < 2; i++) {
                    mma16816(du[i][j], ah[i], bh);
                    mma16816(du[i][j], ah[i], bl);
                    mma16816(du[i][j], al[i], bh);
                }
            }
        }
        // store chunk c+1 into stage nxt
        if (c + 1 < NC) {
            char* st = smem + nxt;
            *(uint4*)(st + OAH + (am * A_STR + ak) * 2) = ahv[0];
            *(uint4*)(st + OAH + (am * A_STR + ak + 8) * 2) = ahv[1];
            *(uint4*)(st + OAL + (am * A_STR + ak) * 2) = alv[0];
            *(uint4*)(st + OAL + (am * A_STR + ak + 8) * 2) = alv[1];
            uint32_t h[8], l[8];
            split16(vb, h, l);
            *(uint4*)(st + obh + (bk * B1_STR + bn) * 2) = make_uint4(h[0], h[1], h[2], h[3]);
            *(uint4*)(st + obh + (bk * B1_STR + bn + 8) * 2) = make_uint4(h[4], h[5], h[6], h[7]);
            *(uint4*)(st + obl + (bk * B1_STR + bn) * 2) = make_uint4(l[0], l[1], l[2], l[3]);
            *(uint4*)(st + obl + (bk * B1_STR + bn + 8) * 2) = make_uint4(l[4], l[5], l[6], l[7]);
        }
        __syncthreads();
    }

    // epilogue: silu(g)*u -> act hi/lo (bf16 split)
#pragma unroll
    for (int i = 0; i < 2; i++)
#pragma unroll
        for (int h2 = 0; h2 < 2; h2++) {
            int m = m0 + wm * 32 + i * 16 + h2 * 8 + (lane >> 2);
            if (m < cnt) {
                size_t rowb = (size_t)(seg + m) * NI + c0 + wn * 32 + (lane & 3) * 2;
#pragma unroll
                for (int j = 0; j < 4; j++) {
                    float g0 = dg[i][j][h2 * 2], g1 = dg[i][j][h2 * 2 + 1];
                    float u0 = du[i][j][h2 * 2], u1 = du[i][j][h2 * 2 + 1];
                    float r0 = g0 / (1.f + __expf(-g0)) * u0;
                    float r1 = g1 / (1.f + __expf(-g1)) * u1;
                    uint32_t hh, ll;
                    fsplit2(r0, r1, hh, ll);
                    *(uint32_t*)&g_act_hi[rowb + j * 8] = hh;
                    *(uint32_t*)&g_act_lo[rowb + j * 8] = ll;
                }
            }
        }
}

// ---------------- launch 4: GEMM2 y = act @ Wd ----------------
// CTA 128m x 128n, BK=32, double-buffered, warp tile 32x64.
#define STG2 37888
__global__ __launch_bounds__(256)
void k_down(const float* __restrict__ wd) {
    const int e   = blockIdx.z;
    const int cnt = g_cnt[e];
    const int m0  = blockIdx.x * 128;
    if (m0 >= cnt) return;
    const int seg = g_off[e];
    const int h0  = blockIdx.y * 128;

    extern __shared__ char smem[];

    const int tid = threadIdx.x;
    const int lane = tid & 31, wid = tid >> 5;
    const int wm = wid & 3, wn = wid >> 2;

    const int am = tid >> 1, ak = (tid & 1) * 16;
    const int aslot = seg + ((m0 + am < cnt) ? (m0 + am) : 0);
    const uint16_t* pah = g_act_hi + (size_t)aslot * NI + ak;
    const uint16_t* pal = g_act_lo + (size_t)aslot * NI + ak;

    const int bk = tid >> 3, bn = (tid & 7) * 16;
    const float* apB = wd + (size_t)e * NI * NH + (size_t)bk * NH + h0 + bn;

    const uint32_t sb = smem_u32(smem);
    const uint32_t OAH = 0, OAL = 10240, OBH = 20480, OBL = 29184;

    float acc[2][8][4];
#pragma unroll
    for (int i = 0; i < 2; i++)
#pragma unroll
        for (int j = 0; j < 8; j++)
#pragma unroll
            for (int q = 0; q < 4; q++) acc[i][j][q] = 0.f;

    uint4 ahv[2], alv[2];
    float vb[16];
    ahv[0] = ((const uint4*)pah)[0]; ahv[1] = ((const uint4*)pah)[1];
    alv[0] = ((const uint4*)pal)[0]; alv[1] = ((const uint4*)pal)[1];
#pragma unroll
    for (int q = 0; q < 4; q++) {
        float4 s = ((const float4*)apB)[q];
        vb[4 * q] = s.x; vb[4 * q + 1] = s.y; vb[4 * q + 2] = s.z; vb[4 * q + 3] = s.w;
    }
    {
        char* st = smem;
        *(uint4*)(st + OAH + (am * A_STR + ak) * 2) = ahv[0];
        *(uint4*)(st + OAH + (am * A_STR + ak + 8) * 2) = ahv[1];
        *(uint4*)(st + OAL + (am * A_STR + ak) * 2) = alv[0];
        *(uint4*)(st + OAL + (am * A_STR + ak + 8) * 2) = alv[1];
        uint32_t h[8], l[8];
        split16(vb, h, l);
        *(uint4*)(st + OBH + (bk * B2_STR + bn) * 2) = make_uint4(h[0], h[1], h[2], h[3]);
        *(uint4*)(st + OBH + (bk * B2_STR + bn + 8) * 2) = make_uint4(h[4], h[5], h[6], h[7]);
        *(uint4*)(st + OBL + (bk * B2_STR + bn) * 2) = make_uint4(l[0], l[1], l[2], l[3]);
        *(uint4*)(st + OBL + (bk * B2_STR + bn + 8) * 2) = make_uint4(l[4], l[5], l[6], l[7]);
    }
    __syncthreads();

    const int NC = NI / 32;
    for (int c = 0; c < NC; c++) {
        const uint32_t cur = (uint32_t)(c & 1) * STG2;
        const uint32_t nxt = cur ^ STG2;
        if (c + 1 < NC) {
            const uint16_t* ph = pah + (c + 1) * 32;
            const uint16_t* pl = pal + (c + 1) * 32;
            ahv[0] = ((const uint4*)ph)[0]; ahv[1] = ((const uint4*)ph)[1];
            alv[0] = ((const uint4*)pl)[0]; alv[1] = ((const uint4*)pl)[1];
            const float* pb = apB + (size_t)(c + 1) * 32 * NH;
#pragma unroll
            for (int q = 0; q < 4; q++) {
                float4 s = ((const float4*)pb)[q];
                vb[4 * q] = s.x; vb[4 * q + 1] = s.y; vb[4 * q + 2] = s.z; vb[4 * q + 3] = s.w;
            }
        }
#pragma unroll
        for (int ks = 0; ks < 2; ks++) {
            const int k16 = ks * 16;
            uint32_t ah[2][4], al[2][4];
#pragma unroll
            for (int i = 0; i < 2; i++) {
                int row = wm * 32 + i * 16 + (lane & 15);
                int col = k16 + (lane >> 4) * 8;
                uint32_t off = (uint32_t)(row * A_STR + col) * 2;
                ldsm_x4(ah[i], sb + cur + OAH + off);
                ldsm_x4(al[i], sb + cur + OAL + off);
            }
#pragma unroll
            for (int j = 0; j < 8; j++) {
                int n = wn * 64 + j * 8;
                uint32_t off = (uint32_t)((k16 + (lane & 15)) * B2_STR + n) * 2;
                uint32_t bh[2], bl[2];
                ldsm_x2t(bh, sb + cur + OBH + off);
                ldsm_x2t(bl, sb + cur + OBL + off);
#pragma unroll
                for (int i = 0; i < 2; i++) {
                    mma16816(acc[i][j], ah[i], bh);
                    mma16816(acc[i][j], ah[i], bl);
                    mma16816(acc[i][j], al[i], bh);
                }
            }
        }
        if (c + 1 < NC) {
            char* st = smem + nxt;
            *(uint4*)(st + OAH + (am * A_STR + ak) * 2) = ahv[0];
            *(uint4*)(st + OAH + (am * A_STR + ak + 8) * 2) = ahv[1];
            *(uint4*)(st + OAL + (am * A_STR + ak) * 2) = alv[0];
            *(uint4*)(st + OAL + (am * A_STR + ak + 8) * 2) = alv[1];
            uint32_t h[8], l[8];
            split16(vb, h, l);
            *(uint4*)(st + OBH + (bk * B2_STR + bn) * 2) = make_uint4(h[0], h[1], h[2], h[3]);
            *(uint4*)(st + OBH + (bk * B2_STR + bn + 8) * 2) = make_uint4(h[4], h[5], h[6], h[7]);
            *(uint4*)(st + OBL + (bk * B2_STR + bn) * 2) = make_uint4(l[0], l[1], l[2], l[3]);
            *(uint4*)(st + OBL + (bk * B2_STR + bn + 8) * 2) = make_uint4(l[4], l[5], l[6], l[7]);
        }
        __syncthreads();
    }

#pragma unroll
    for (int i = 0; i < 2; i++)
#pragma unroll
        for (int h2 = 0; h2 < 2; h2++) {
            int m = m0 + wm * 32 + i * 16 + h2 * 8 + (lane >> 2);
            if (m < cnt) {
                float* op = g_y + (size_t)(seg + m) * NH + h0 + wn * 64 + (lane & 3) * 2;
#pragma unroll
                for (int j = 0; j < 8; j++)
                    *(float2*)(op + j * 8) = make_float2(acc[i][j][h2 * 2], acc[i][j][h2 * 2 + 1]);
            }
        }
}

// ---------------- launch 5: combine ----------------
__global__ void k_combine(const float* __restrict__ val, float* __restrict__ out) {
    int i = blockIdx.x * blockDim.x + threadIdx.x;
    if (i >= NT * (NH / 4)) return;
    int t  = i / (NH / 4);
    int h4 = i - t * (NH / 4);
    float4 r = make_float4(0.f, 0.f, 0.f, 0.f);
#pragma unroll
    for (int k = 0; k < NTK; k++) {
        int   p = g_pos[t * NTK + k];
        float w = val[t * NTK + k];
        float4 y = *(const float4*)&g_y[(size_t)p * NH + h4 * 4];
        r.x += w * y.x; r.y += w * y.y; r.z += w * y.z; r.w += w * y.w;
    }
    *(float4*)&out[(size_t)t * NH + h4 * 4] = r;
}

// ---------------- launch ----------------
extern "C" void kernel_launch(void* const* d_in, const int* in_sizes, int n_in,
                              void* d_out, int out_size) {
    const float* hs  = (const float*)d_in[0];
    const int*   idx = (const int*)d_in[1];
    const float* val = (const float*)d_in[2];
    const float* wg  = (const float*)d_in[3];
    const float* wu  = (const float*)d_in[4];
    const float* wd  = (const float*)d_in[5];
    float*       out = (float*)d_out;
    (void)in_sizes; (void)n_in; (void)out_size;

    cudaFuncSetAttribute(k_gate_up, cudaFuncAttributeMaxDynamicSharedMemorySize, 2 * STG1);
    cudaFuncSetAttribute(k_down,    cudaFuncAttributeMaxDynamicSharedMemorySize, 2 * STG2);

    k_route<<<1, 1024>>>(idx);                                  // launch 0
    k_split_x<<<512, 256>>>(hs, 0);                             // launch 1
    k_split_x<<<512, 256>>>(hs, NT / 2);                        // launch 2

    dim3 g1(NA / 128, NI / 64, NE);                             // launch 3 (profiled slot)
    k_gate_up<<<g1, 256, 2 * STG1>>>(wg, wu);

    dim3 g2(NA / 128, NH / 128, NE);                            // launch 4
    k_down<<<g2, 256, 2 * STG2>>>(wd);

    k_combine<<<(NT * (NH / 4) + 255) / 256, 256>>>(val, out);  // launch 5
}

// round 10
// speedup vs baseline: 2.5043x; 1.0452x over previous
#include <cuda_runtime.h>
#include <cuda_bf16.h>
#include <cstdint>

// Problem constants
#define NE  8
#define NH  1024
#define NI  2816
#define NTK 2
#define NT  2048
#define NA  (NT * NTK)
#define NW  (NE * NH * NI)   // weight elems per tensor (gate/up); wd same count

// smem strides (bf16 elements), padded for conflict-free ldmatrix
#define A_STR  40    // 32 + 8
#define B1_STR 72    // 64 + 8
#define B2_STR 136   // 128 + 8

// -------- scratch (static device globals) --------
__device__ int g_cnt[NE];
__device__ int g_off[NE];
__device__ int g_tok[NA];
__device__ int g_pos[NA];
__device__ __align__(16) uint16_t g_xhi[NT * NH];
__device__ __align__(16) uint16_t g_xlo[NT * NH];
__device__ __align__(16) uint16_t g_wg_hi[NW], g_wg_lo[NW];       // 46MB each
__device__ __align__(16) uint16_t g_wu_hi[NW], g_wu_lo[NW];
__device__ __align__(16) uint16_t g_wd_hi[NW], g_wd_lo[NW];
__device__ __align__(16) uint16_t g_act_hi[(size_t)NA * NI];
__device__ __align__(16) uint16_t g_act_lo[(size_t)NA * NI];
__device__ __align__(16) float    g_y[(size_t)NA * NH];

// ---------------- helpers ----------------
__device__ __forceinline__ uint32_t smem_u32(const void* p) {
    uint32_t a;
    asm("{ .reg .u64 t; cvta.to.shared.u64 t, %1; cvt.u32.u64 %0, t; }" : "=r"(a) : "l"(p));
    return a;
}
__device__ __forceinline__ void cpa16(uint32_t s, const void* g) {
    asm volatile("cp.async.cg.shared.global [%0], [%1], 16;" :: "r"(s), "l"(g));
}
__device__ __forceinline__ void cpa_commit() {
    asm volatile("cp.async.commit_group;" ::: "memory");
}
__device__ __forceinline__ void cpa_wait0() {
    asm volatile("cp.async.wait_group 0;" ::: "memory");
}
__device__ __forceinline__ void ldsm_x4(uint32_t* r, uint32_t a) {
    asm volatile("ldmatrix.sync.aligned.m8n8.x4.shared.b16 {%0,%1,%2,%3}, [%4];"
                 : "=r"(r[0]), "=r"(r[1]), "=r"(r[2]), "=r"(r[3]) : "r"(a));
}
__device__ __forceinline__ void ldsm_x2t(uint32_t* r, uint32_t a) {
    asm volatile("ldmatrix.sync.aligned.m8n8.x2.trans.shared.b16 {%0,%1}, [%2];"
                 : "=r"(r[0]), "=r"(r[1]) : "r"(a));
}
__device__ __forceinline__ void mma16816(float* d, const uint32_t* a, const uint32_t* b) {
    asm volatile("mma.sync.aligned.m16n8k16.row.col.f32.bf16.bf16.f32 "
                 "{%0,%1,%2,%3}, {%4,%5,%6,%7}, {%8,%9}, {%0,%1,%2,%3};"
                 : "+f"(d[0]), "+f"(d[1]), "+f"(d[2]), "+f"(d[3])
                 : "r"(a[0]), "r"(a[1]), "r"(a[2]), "r"(a[3]), "r"(b[0]), "r"(b[1]));
}
// fast split: hi = truncated-bf16 (exact top 16 bits), lo = rn-bf16 of residual
__device__ __forceinline__ void fsplit2(float x0, float x1, uint32_t& hi, uint32_t& lo) {
    uint32_t u0 = __float_as_uint(x0), u1 = __float_as_uint(x1);
    hi = __byte_perm(u0, u1, 0x7632);
    float r0 = x0 - __uint_as_float(u0 & 0xFFFF0000u);
    float r1 = x1 - __uint_as_float(u1 & 0xFFFF0000u);
    __nv_bfloat162 p = __floats2bfloat162_rn(r0, r1);
    lo = *(uint32_t*)&p;
}

// ---------------- launch 0: routing ----------------
__global__ void k_route(const int* __restrict__ idx) {
    __shared__ int sc[NE], scur[NE];
    int tid = threadIdx.x;
    if (tid < NE) sc[tid] = 0;
    __syncthreads();
    for (int i = tid; i < NA; i += 1024) atomicAdd(&sc[idx[i]], 1);
    __syncthreads();
    if (tid == 0) {
        int s = 0;
        for (int e = 0; e < NE; e++) { g_cnt[e] = sc[e]; g_off[e] = s; scur[e] = s; s += sc[e]; }
    }
    __syncthreads();
    for (int i = tid; i < NA; i += 1024) {
        int e = idx[i];
        int p = atomicAdd(&scur[e], 1);
        g_tok[p] = i / NTK;
        g_pos[i] = p;
    }
}

// ---------------- launch 1: split X ----------------
__global__ void k_split_x(const float* __restrict__ hs) {
    int i = blockIdx.x * blockDim.x + threadIdx.x;     // one thread per 8 elems
    size_t base = (size_t)i * 8;
    float4 v0 = ((const float4*)(hs + base))[0];
    float4 v1 = ((const float4*)(hs + base))[1];
    float v[8] = {v0.x, v0.y, v0.z, v0.w, v1.x, v1.y, v1.z, v1.w};
    uint32_t h[4], l[4];
#pragma unroll
    for (int p = 0; p < 4; p++) fsplit2(v[2 * p], v[2 * p + 1], h[p], l[p]);
    *(uint4*)&g_xhi[base] = make_uint4(h[0], h[1], h[2], h[3]);
    *(uint4*)&g_xlo[base] = make_uint4(l[0], l[1], l[2], l[3]);
}

// ---------------- launches 2-4: split weights ----------------
__global__ void k_split_w(const float* __restrict__ src,
                          uint16_t* __restrict__ dhi, uint16_t* __restrict__ dlo) {
    size_t i = (size_t)(blockIdx.x * blockDim.x + threadIdx.x) * 8;
    float4 v0 = ((const float4*)(src + i))[0];
    float4 v1 = ((const float4*)(src + i))[1];
    float v[8] = {v0.x, v0.y, v0.z, v0.w, v1.x, v1.y, v1.z, v1.w};
    uint32_t h[4], l[4];
#pragma unroll
    for (int p = 0; p < 4; p++) fsplit2(v[2 * p], v[2 * p + 1], h[p], l[p]);
    *(uint4*)&dhi[i] = make_uint4(h[0], h[1], h[2], h[3]);
    *(uint4*)&dlo[i] = make_uint4(l[0], l[1], l[2], l[3]);
}

// ---------------- launch 5: GEMM1 act = silu(X@Wg)*(X@Wu) ----------------
// CTA 128m x 64n (gate+up), BK=32, double-buffered cp.async, 8 warps 4m x 2n.
#define STG1 38912
__global__ __launch_bounds__(256, 2)
void k_gate_up() {
    const int e   = blockIdx.z;
    const int cnt = g_cnt[e];
    const int m0  = blockIdx.x * 128;
    if (m0 >= cnt) return;
    const int seg = g_off[e];
    const int c0  = blockIdx.y * 64;

    extern __shared__ char smem[];
    __shared__ int rows[128];

    const int tid = threadIdx.x;
    const int lane = tid & 31, wid = tid >> 5;
    const int wm = wid & 3, wn = wid >> 2;

    if (tid < 128) rows[tid] = (m0 + tid < cnt) ? g_tok[seg + m0 + tid] : g_tok[seg];
    __syncthreads();

    // A: row am, 16 cols starting at ak
    const int am = tid >> 1, ak = (tid & 1) * 16;
    const int arow = rows[am];
    const uint16_t* pxh = g_xhi + (size_t)arow * NH + ak;
    const uint16_t* pxl = g_xlo + (size_t)arow * NH + ak;

    // B: half 0 = gate, 1 = up; row bk, 16 cols at bn
    const int half = tid >> 7;
    const int bt = tid & 127;
    const int bk = bt >> 2, bn = (bt & 3) * 16;
    const size_t boff = (size_t)e * NH * NI + (size_t)bk * NI + c0 + bn;
    const uint16_t* pbh = (half ? g_wu_hi : g_wg_hi) + boff;
    const uint16_t* pbl = (half ? g_wu_lo : g_wg_lo) + boff;

    const uint32_t sb = smem_u32(smem);
    const uint32_t OAH = 0, OAL = 10240, OGH = 20480, OGL = 25088, OUH = 29696, OUL = 34304;
    const uint32_t obh = half ? OUH : OGH;
    const uint32_t obl = half ? OUL : OGL;
    const uint32_t dA  = sb + OAH + (uint32_t)(am * A_STR + ak) * 2;
    const uint32_t dAl = sb + OAL + (uint32_t)(am * A_STR + ak) * 2;
    const uint32_t dB  = sb + obh + (uint32_t)(bk * B1_STR + bn) * 2;
    const uint32_t dBl = sb + obl + (uint32_t)(bk * B1_STR + bn) * 2;

    float dg[2][4][4], du[2][4][4];
#pragma unroll
    for (int i = 0; i < 2; i++)
#pragma unroll
        for (int j = 0; j < 4; j++)
#pragma unroll
            for (int q = 0; q < 4; q++) { dg[i][j][q] = 0.f; du[i][j][q] = 0.f; }

#define LOAD1(st, c)                                                     \
    do {                                                                 \
        const uint16_t* _ah = pxh + (c) * 32;                            \
        const uint16_t* _al = pxl + (c) * 32;                            \
        const uint16_t* _bh = pbh + (size_t)(c) * 32 * NI;               \
        const uint16_t* _bl = pbl + (size_t)(c) * 32 * NI;               \
        cpa16(dA + (st), _ah);      cpa16(dA + (st) + 16, _ah + 8);      \
        cpa16(dAl + (st), _al);     cpa16(dAl + (st) + 16, _al + 8);     \
        cpa16(dB + (st), _bh);      cpa16(dB + (st) + 16, _bh + 8);      \
        cpa16(dBl + (st), _bl);     cpa16(dBl + (st) + 16, _bl + 8);     \
    } while (0)

    LOAD1(0, 0);
    cpa_commit();
    cpa_wait0();
    __syncthreads();

    const int NC = NH / 32;
    for (int c = 0; c < NC; c++) {
        const uint32_t cur = (uint32_t)(c & 1) * STG1;
        const uint32_t nxt = cur ^ STG1;
        if (c + 1 < NC) { LOAD1(nxt, c + 1); cpa_commit(); }

#pragma unroll
        for (int ks = 0; ks < 2; ks++) {
            const int k16 = ks * 16;
            uint32_t ah[2][4], al[2][4];
#pragma unroll
            for (int i = 0; i < 2; i++) {
                int row = wm * 32 + i * 16 + (lane & 15);
                int col = k16 + (lane >> 4) * 8;
                uint32_t off = (uint32_t)(row * A_STR + col) * 2;
                ldsm_x4(ah[i], sb + cur + OAH + off);
                ldsm_x4(al[i], sb + cur + OAL + off);
            }
#pragma unroll
            for (int j = 0; j < 4; j++) {
                int n = wn * 32 + j * 8;
                uint32_t off = (uint32_t)((k16 + (lane & 15)) * B1_STR + n) * 2;
                uint32_t bh[2], bl[2];
                ldsm_x2t(bh, sb + cur + OGH + off);
                ldsm_x2t(bl, sb + cur + OGL + off);
#pragma unroll
                for (int i = 0; i < 2; i++) {
                    mma16816(dg[i][j], ah[i], bh);
                    mma16816(dg[i][j], ah[i], bl);
                    mma16816(dg[i][j], al[i], bh);
                }
                ldsm_x2t(bh, sb + cur + OUH + off);
                ldsm_x2t(bl, sb + cur + OUL + off);
#pragma unroll
                for (int i = 0; i < 2; i++) {
                    mma16816(du[i][j], ah[i], bh);
                    mma16816(du[i][j], ah[i], bl);
                    mma16816(du[i][j], al[i], bh);
                }
            }
        }
        if (c + 1 < NC) cpa_wait0();
        __syncthreads();
    }
#undef LOAD1

    // epilogue: silu(g)*u -> act hi/lo
#pragma unroll
    for (int i = 0; i < 2; i++)
#pragma unroll
        for (int h2 = 0; h2 < 2; h2++) {
            int m = m0 + wm * 32 + i * 16 + h2 * 8 + (lane >> 2);
            if (m < cnt) {
                size_t rowb = (size_t)(seg + m) * NI + c0 + wn * 32 + (lane & 3) * 2;
#pragma unroll
                for (int j = 0; j < 4; j++) {
                    float g0 = dg[i][j][h2 * 2], g1 = dg[i][j][h2 * 2 + 1];
                    float u0 = du[i][j][h2 * 2], u1 = du[i][j][h2 * 2 + 1];
                    float r0 = g0 / (1.f + __expf(-g0)) * u0;
                    float r1 = g1 / (1.f + __expf(-g1)) * u1;
                    uint32_t hh, ll;
                    fsplit2(r0, r1, hh, ll);
                    *(uint32_t*)&g_act_hi[rowb + j * 8] = hh;
                    *(uint32_t*)&g_act_lo[rowb + j * 8] = ll;
                }
            }
        }
}

// ---------------- launch 6: GEMM2 y = act @ Wd ----------------
// CTA 128m x 128n, BK=32, double-buffered cp.async, warp tile 32x64.
#define STG2 37888
__global__ __launch_bounds__(256, 2)
void k_down() {
    const int e   = blockIdx.z;
    const int cnt = g_cnt[e];
    const int m0  = blockIdx.x * 128;
    if (m0 >= cnt) return;
    const int seg = g_off[e];
    const int h0  = blockIdx.y * 128;

    extern __shared__ char smem[];

    const int tid = threadIdx.x;
    const int lane = tid & 31, wid = tid >> 5;
    const int wm = wid & 3, wn = wid >> 2;

    const int am = tid >> 1, ak = (tid & 1) * 16;
    const int aslot = seg + ((m0 + am < cnt) ? (m0 + am) : 0);
    const uint16_t* pah = g_act_hi + (size_t)aslot * NI + ak;
    const uint16_t* pal = g_act_lo + (size_t)aslot * NI + ak;

    const int bk = tid >> 3, bn = (tid & 7) * 16;
    const size_t boff = (size_t)e * NI * NH + (size_t)bk * NH + h0 + bn;
    const uint16_t* pbh = g_wd_hi + boff;
    const uint16_t* pbl = g_wd_lo + boff;

    const uint32_t sb = smem_u32(smem);
    const uint32_t OAH = 0, OAL = 10240, OBH = 20480, OBL = 29184;
    const uint32_t dA  = sb + OAH + (uint32_t)(am * A_STR + ak) * 2;
    const uint32_t dAl = sb + OAL + (uint32_t)(am * A_STR + ak) * 2;
    const uint32_t dB  = sb + OBH + (uint32_t)(bk * B2_STR + bn) * 2;
    const uint32_t dBl = sb + OBL + (uint32_t)(bk * B2_STR + bn) * 2;

    float acc[2][8][4];
#pragma unroll
    for (int i = 0; i < 2; i++)
#pragma unroll
        for (int j = 0; j < 8; j++)
#pragma unroll
            for (int q = 0; q < 4; q++) acc[i][j][q] = 0.f;

#define LOAD2(st, c)                                                     \
    do {                                                                 \
        const uint16_t* _ah = pah + (c) * 32;                            \
        const uint16_t* _al = pal + (c) * 32;                            \
        const uint16_t* _bh = pbh + (size_t)(c) * 32 * NH;               \
        const uint16_t* _bl = pbl + (size_t)(c) * 32 * NH;               \
        cpa16(dA + (st), _ah);      cpa16(dA + (st) + 16, _ah + 8);      \
        cpa16(dAl + (st), _al);     cpa16(dAl + (st) + 16, _al + 8);     \
        cpa16(dB + (st), _bh);      cpa16(dB + (st) + 16, _bh + 8);      \
        cpa16(dBl + (st), _bl);     cpa16(dBl + (st) + 16, _bl + 8);     \
    } while (0)

    LOAD2(0, 0);
    cpa_commit();
    cpa_wait0();
    __syncthreads();

    const int NC = NI / 32;
    for (int c = 0; c < NC; c++) {
        const uint32_t cur = (uint32_t)(c & 1) * STG2;
        const uint32_t nxt = cur ^ STG2;
        if (c + 1 < NC) { LOAD2(nxt, c + 1); cpa_commit(); }

#pragma unroll
        for (int ks = 0; ks < 2; ks++) {
            const int k16 = ks * 16;
            uint32_t ah[2][4], al[2][4];
#pragma unroll
            for (int i = 0; i < 2; i++) {
                int row = wm * 32 + i * 16 + (lane & 15);
                int col = k16 + (lane >> 4) * 8;
                uint32_t off = (uint32_t)(row * A_STR + col) * 2;
                ldsm_x4(ah[i], sb + cur + OAH + off);
                ldsm_x4(al[i], sb + cur + OAL + off);
            }
#pragma unroll
            for (int j = 0; j < 8; j++) {
                int n = wn * 64 + j * 8;
                uint32_t off = (uint32_t)((k16 + (lane & 15)) * B2_STR + n) * 2;
                uint32_t bh[2], bl[2];
                ldsm_x2t(bh, sb + cur + OBH + off);
                ldsm_x2t(bl, sb + cur + OBL + off);
#pragma unroll
                for (int i = 0; i < 2; i++) {
                    mma16816(acc[i][j], ah[i], bh);
                    mma16816(acc[i][j], ah[i], bl);
                    mma16816(acc[i][j], al[i], bh);
                }
            }
        }
        if (c + 1 < NC) cpa_wait0();
        __syncthreads();
    }
#undef LOAD2

#pragma unroll
    for (int i = 0; i < 2; i++)
#pragma unroll
        for (int h2 = 0; h2 < 2; h2++) {
            int m = m0 + wm * 32 + i * 16 + h2 * 8 + (lane >> 2);
            if (m < cnt) {
                float* op = g_y + (size_t)(seg + m) * NH + h0 + wn * 64 + (lane & 3) * 2;
#pragma unroll
                for (int j = 0; j < 8; j++)
                    *(float2*)(op + j * 8) = make_float2(acc[i][j][h2 * 2], acc[i][j][h2 * 2 + 1]);
            }
        }
}

// ---------------- launch 7: combine ----------------
__global__ void k_combine(const float* __restrict__ val, float* __restrict__ out) {
    int i = blockIdx.x * blockDim.x + threadIdx.x;
    if (i >= NT * (NH / 4)) return;
    int t  = i / (NH / 4);
    int h4 = i - t * (NH / 4);
    float4 r = make_float4(0.f, 0.f, 0.f, 0.f);
#pragma unroll
    for (int k = 0; k < NTK; k++) {
        int   p = g_pos[t * NTK + k];
        float w = val[t * NTK + k];
        float4 y = *(const float4*)&g_y[(size_t)p * NH + h4 * 4];
        r.x += w * y.x; r.y += w * y.y; r.z += w * y.z; r.w += w * y.w;
    }
    *(float4*)&out[(size_t)t * NH + h4 * 4] = r;
}

// ---------------- launch ----------------
extern "C" void kernel_launch(void* const* d_in, const int* in_sizes, int n_in,
                              void* d_out, int out_size) {
    const float* hs  = (const float*)d_in[0];
    const int*   idx = (const int*)d_in[1];
    const float* val = (const float*)d_in[2];
    const float* wg  = (const float*)d_in[3];
    const float* wu  = (const float*)d_in[4];
    const float* wd  = (const float*)d_in[5];
    float*       out = (float*)d_out;
    (void)in_sizes; (void)n_in; (void)out_size;

    cudaFuncSetAttribute(k_gate_up, cudaFuncAttributeMaxDynamicSharedMemorySize, 2 * STG1);
    cudaFuncSetAttribute(k_down,    cudaFuncAttributeMaxDynamicSharedMemorySize, 2 * STG2);

    uint16_t *wg_hi, *wg_lo, *wu_hi, *wu_lo, *wd_hi, *wd_lo;
    cudaGetSymbolAddress((void**)&wg_hi, g_wg_hi);
    cudaGetSymbolAddress((void**)&wg_lo, g_wg_lo);
    cudaGetSymbolAddress((void**)&wu_hi, g_wu_hi);
    cudaGetSymbolAddress((void**)&wu_lo, g_wu_lo);
    cudaGetSymbolAddress((void**)&wd_hi, g_wd_hi);
    cudaGetSymbolAddress((void**)&wd_lo, g_wd_lo);

    k_route<<<1, 1024>>>(idx);                                  // 0
    k_split_x<<<NT * NH / 8 / 256, 256>>>(hs);                  // 1
    k_split_w<<<NW / 8 / 256, 256>>>(wg, wg_hi, wg_lo);         // 2
    k_split_w<<<NW / 8 / 256, 256>>>(wu, wu_hi, wu_lo);         // 3
    k_split_w<<<NW / 8 / 256, 256>>>(wd, wd_hi, wd_lo);         // 4

    dim3 g1(NA / 128, NI / 64, NE);                             // 5 (profiled slot)
    k_gate_up<<<g1, 256, 2 * STG1>>>();

    dim3 g2(NA / 128, NH / 128, NE);                            // 6
    k_down<<<g2, 256, 2 * STG2>>>();

    k_combine<<<(NT * (NH / 4) + 255) / 256, 256>>>(val, out);  // 7
}